// round 16
// baseline (speedup 1.0000x reference)
#include <cuda_runtime.h>

#define VOCABN 1000
#define EMBN   128
#define HIDN   256
#define G4N    1024   // 4*HID
#define BN     64
#define TN     1024

#define CL     8      // CTAs per cluster
#define GB     4      // batch rows per cluster
#define NTH    512    // 64 row-pairs x 8 k-eighths

// Precomputed per-vocab gate projections: proj[v][g] = emb[v].W_ih[g] + b_ih[g] + b_hh[g]
__device__ float g_proj[VOCABN * G4N];

// ---------------- packed f32x2 helpers ----------------
__device__ __forceinline__ unsigned long long fma2(unsigned long long a,
                                                   unsigned long long b,
                                                   unsigned long long c) {
    unsigned long long d;
    asm("fma.rn.f32x2 %0, %1, %2, %3;" : "=l"(d) : "l"(a), "l"(b), "l"(c));
    return d;
}
__device__ __forceinline__ unsigned long long add2(unsigned long long a,
                                                   unsigned long long b) {
    unsigned long long d;
    asm("add.rn.f32x2 %0, %1, %2;" : "=l"(d) : "l"(a), "l"(b));
    return d;
}
__device__ __forceinline__ float lo32(unsigned long long v) {
    return __uint_as_float((unsigned)v);
}
__device__ __forceinline__ float hi32(unsigned long long v) {
    return __uint_as_float((unsigned)(v >> 32));
}

__device__ __forceinline__ float sigf(float x) {
    return __fdividef(1.0f, 1.0f + __expf(-x));
}
__device__ __forceinline__ float tanhf_(float x) {
    return 1.0f - __fdividef(2.0f, __expf(2.0f * x) + 1.0f);
}

// ---------------- cluster smem / mbarrier helpers ----------------
__device__ __forceinline__ unsigned smem_u32(const void* p) {
    return (unsigned)__cvta_generic_to_shared(p);
}
__device__ __forceinline__ void mbar_init(unsigned a, unsigned cnt) {
    asm volatile("mbarrier.init.shared.b64 [%0], %1;" :: "r"(a), "r"(cnt) : "memory");
}
__device__ __forceinline__ unsigned mapa_u32(unsigned a, unsigned rank) {
    unsigned r;
    asm("mapa.shared::cluster.u32 %0, %1, %2;" : "=r"(r) : "r"(a), "r"(rank));
    return r;
}
__device__ __forceinline__ void mbar_arm(unsigned a, unsigned tx_bytes) {
    asm volatile("mbarrier.arrive.expect_tx.shared.b64 _, [%0], %1;"
                 :: "r"(a), "r"(tx_bytes) : "memory");
}
// remote vector store (16 B), counts bytes into the destination's mbarrier
__device__ __forceinline__ void st_async_f32x4(unsigned dst, float v0, float v1,
                                               float v2, float v3, unsigned mb) {
    asm volatile(
        "st.async.shared::cluster.mbarrier::complete_tx::bytes.v4.b32 "
        "[%0], {%1, %2, %3, %4}, [%5];"
        :: "r"(dst), "r"(__float_as_uint(v0)), "r"(__float_as_uint(v1)),
           "r"(__float_as_uint(v2)), "r"(__float_as_uint(v3)), "r"(mb)
        : "memory");
}
__device__ __forceinline__ void mbar_wait(unsigned a, unsigned parity) {
    asm volatile(
        "{\n\t"
        ".reg .pred P;\n\t"
        "mbarrier.try_wait.parity.acquire.cluster.shared::cta.b64 P, [%0], %1;\n\t"
        "@P bra.uni WDONE_%=;\n\t"
        "WLOOP_%=:\n\t"
        "mbarrier.try_wait.parity.acquire.cluster.shared::cta.b64 P, [%0], %1, 0x989680;\n\t"
        "@!P bra.uni WLOOP_%=;\n\t"
        "WDONE_%=:\n\t"
        "}"
        :: "r"(a), "r"(parity) : "memory");
}
__device__ __forceinline__ void bar_sync_id(int id, int cnt) {
    asm volatile("bar.sync %0, %1;" :: "r"(id), "r"(cnt) : "memory");
}
__device__ __forceinline__ void bar_arrive_id(int id, int cnt) {
    asm volatile("bar.arrive %0, %1;" :: "r"(id), "r"(cnt) : "memory");
}
__device__ __forceinline__ void cluster_sync_once() {
    asm volatile("barrier.cluster.arrive.aligned;" ::: "memory");
    asm volatile("barrier.cluster.wait.aligned;" ::: "memory");
}

// ---------------------------------------------------------------------------
// Kernel 1: vocab projection table. 125 blocks x 256 threads, 8 vocab/block.
// ---------------------------------------------------------------------------
__global__ void __launch_bounds__(256) proj_kernel(
    const float* __restrict__ emb, const float* __restrict__ W_ih,
    const float* __restrict__ b_ih, const float* __restrict__ b_hh)
{
    __shared__ float4 es4[8][EMBN / 4];
    const int v0 = blockIdx.x * 8;
    const int tid = threadIdx.x;
    for (int i = tid; i < 8 * EMBN; i += 256) {
        int v = i >> 7, e = i & 127;
        ((float*)es4)[v * EMBN + e] = emb[(v0 + v) * EMBN + e];
    }
    __syncthreads();

    const float4* W4 = (const float4*)W_ih;
#pragma unroll
    for (int rr = 0; rr < 4; rr++) {
        int g = tid + rr * 256;
        float acc[8];
#pragma unroll
        for (int v = 0; v < 8; v++) acc[v] = 0.f;
        for (int e4 = 0; e4 < EMBN / 4; e4++) {
            float4 w = W4[g * (EMBN / 4) + e4];
#pragma unroll
            for (int v = 0; v < 8; v++) {
                float4 x = es4[v][e4];
                acc[v] += w.x * x.x + w.y * x.y + w.z * x.z + w.w * x.w;
            }
        }
        float bias = b_ih[g] + b_hh[g];
#pragma unroll
        for (int v = 0; v < 8; v++)
            g_proj[(v0 + v) * G4N + g] = acc[v] + bias;
    }
}

// ---------------------------------------------------------------------------
// Kernel 2: recurrence. 16 clusters x 8 CTAs; cluster owns 4 batch rows.
// Matvec = R15 (thread = row-pair rp x k-eighth q; W 2 rows in 32 u64 regs;
// 32 LDS.128 + 128 FFMA2/thread). NEW: psum double-buffered by step parity
// and the step barrier is SPLIT — producer warps 4..15 bar.arrive and run
// straight into the next step's mbar wait + matvec, while only the 128-thread
// cell crew (warps 0..3) bar.syncs, reduces (packed add2 over the float2
// psum: {i,g} at [h], {f,o} at [32+h]), runs the cell, and pushes h_new via
// st.async.v4. The cell tail overlaps the producers' next matvec.
// ---------------------------------------------------------------------------
__global__ void __launch_bounds__(NTH, 1) __cluster_dims__(CL, 1, 1)
lstm_kernel(const int* __restrict__ tokens, const int* __restrict__ lengths,
            const float* __restrict__ W_hh, float* __restrict__ out)
{
    __shared__ float  hb[2][GB][HIDN];         // 8 KB: double-buffered h, batch-major
    __shared__ float2 psv[2][8][GB][64];       // 32 KB: [buf][eighth][batch][row-pair]
    __shared__ __align__(8) unsigned long long mbar[2];

    const int rank = blockIdx.x;               // 0..7
    const int cid  = blockIdx.y;               // 0..15
    const int tid  = threadIdx.x;
    const int rp   = tid & 63;                 // row-pair 0..63
    const int q    = tid >> 6;                 // k-eighth 0..7 (warp-uniform)
    const int base = rank * 32;
    const int b0   = cid * GB;
    const unsigned TXB = 4096;                 // bytes per exchange phase
    const int hI   = rp & 31;
    const int gI   = rp >> 5;                  // gates gI and gI+2
    const int grow0 = gI * HIDN + base + hI;
    const int grow1 = grow0 + 2 * HIDN;

    // --- W slices into registers: 2 rows x 32 floats = 2 x 16 pairs ---
    unsigned long long w0[16], w1[16];
    {
        const ulonglong2* wr0 =
            (const ulonglong2*)(W_hh + (size_t)grow0 * HIDN + q * 32);
        const ulonglong2* wr1 =
            (const ulonglong2*)(W_hh + (size_t)grow1 * HIDN + q * 32);
#pragma unroll
        for (int j = 0; j < 8; j++) {
            ulonglong2 a = wr0[j];
            ulonglong2 b = wr1[j];
            w0[2 * j] = a.x; w0[2 * j + 1] = a.y;
            w1[2 * j] = b.x; w1[2 * j + 1] = b.y;
        }
    }

    const unsigned mb0 = smem_u32(&mbar[0]);
    const unsigned mb1 = smem_u32(&mbar[1]);
    if (tid == 0) {
        mbar_init(mb0, 1);
        mbar_init(mb1, 1);
        mbar_arm(mb1, TXB);    // pre-arm for t=1 data (arrives into hb[1])
    }
    for (int i = tid; i < GB * HIDN; i += NTH) ((float*)hb[0])[i] = 0.f;
    __syncthreads();
    cluster_sync_once();       // init + hb[0]=0 visible cluster-wide

    // cell crew identity (tid<128): one thread per (h index, batch)
    const int ch = tid & 31;        // h index
    const int cb = tid >> 5;        // batch 0..3 (for tid<128)
    const int mylen = (tid < 128) ? lengths[b0 + cb] : 0;

    const int len0 = lengths[b0 + 0];
    const int len1 = lengths[b0 + 1];
    const int len2 = lengths[b0 + 2];
    const int len3 = lengths[b0 + 3];
    int steps = max(max(len0, len1), max(len2, len3));
    if (steps > TN) steps = TN;

    // input projections: q==0 threads (tid<64) hold both rows x 4 batches
    float xwA0 = 0.f, xwA1 = 0.f, xwA2 = 0.f, xwA3 = 0.f;
    float xwB0 = 0.f, xwB1 = 0.f, xwB2 = 0.f, xwB3 = 0.f;
    if (q == 0) {
        int t0 = tokens[(b0 + 0) * TN], t1 = tokens[(b0 + 1) * TN];
        int t2 = tokens[(b0 + 2) * TN], t3 = tokens[(b0 + 3) * TN];
        xwA0 = g_proj[t0 * G4N + grow0]; xwB0 = g_proj[t0 * G4N + grow1];
        xwA1 = g_proj[t1 * G4N + grow0]; xwB1 = g_proj[t1 * G4N + grow1];
        xwA2 = g_proj[t2 * G4N + grow0]; xwB2 = g_proj[t2 * G4N + grow1];
        xwA3 = g_proj[t3 * G4N + grow0]; xwB3 = g_proj[t3 * G4N + grow1];
    }

    float creg = 0.f, hreg = 0.f;
    unsigned ph0 = 0, ph1 = 0;
    const int lane = tid & 31;

    for (int t = 0; t < steps; t++) {
        const int buf = t & 1;
        // wait for h(t) (skip t=0: hb[0] prezeroed), then re-arm this barrier
        // for the phase two steps ahead.
        if (t) {
            if (buf) { mbar_wait(mb1, ph1); ph1 ^= 1; }
            else     { mbar_wait(mb0, ph0); ph0 ^= 1; }
        }
        if (tid == 0) mbar_arm(buf ? mb1 : mb0, TXB);

        // prefetch next step's input projections (hidden behind the matvec)
        float xnA0, xnA1, xnA2, xnA3, xnB0, xnB1, xnB2, xnB3;
        if (q == 0) {
            int tn = min(t + 1, TN - 1);
            int t0 = tokens[(b0 + 0) * TN + tn], t1 = tokens[(b0 + 1) * TN + tn];
            int t2 = tokens[(b0 + 2) * TN + tn], t3 = tokens[(b0 + 3) * TN + tn];
            xnA0 = g_proj[t0 * G4N + grow0]; xnB0 = g_proj[t0 * G4N + grow1];
            xnA1 = g_proj[t1 * G4N + grow0]; xnB1 = g_proj[t1 * G4N + grow1];
            xnA2 = g_proj[t2 * G4N + grow0]; xnB2 = g_proj[t2 * G4N + grow1];
            xnA3 = g_proj[t3 * G4N + grow0]; xnB3 = g_proj[t3 * G4N + grow1];
        }

        // packed matvec: 2 gate rows, my k-eighth, 4 batches.
        const float* h0p = hb[buf][0] + q * 32;
        const float* h1p = hb[buf][1] + q * 32;
        const float* h2p = hb[buf][2] + q * 32;
        const float* h3p = hb[buf][3] + q * 32;
        unsigned long long aA0 = 0ull, aA1 = 0ull, aA2 = 0ull, aA3 = 0ull;
        unsigned long long aB0 = 0ull, aB1 = 0ull, aB2 = 0ull, aB3 = 0ull;
#pragma unroll
        for (int c = 0; c < 8; c++) {
            ulonglong2 h0 = *(const ulonglong2*)(h0p + c * 4);
            ulonglong2 h1 = *(const ulonglong2*)(h1p + c * 4);
            ulonglong2 h2 = *(const ulonglong2*)(h2p + c * 4);
            ulonglong2 h3 = *(const ulonglong2*)(h3p + c * 4);
            aA0 = fma2(w0[2 * c], h0.x, aA0);
            aA1 = fma2(w0[2 * c], h1.x, aA1);
            aA2 = fma2(w0[2 * c], h2.x, aA2);
            aA3 = fma2(w0[2 * c], h3.x, aA3);
            aB0 = fma2(w1[2 * c], h0.x, aB0);
            aB1 = fma2(w1[2 * c], h1.x, aB1);
            aB2 = fma2(w1[2 * c], h2.x, aB2);
            aB3 = fma2(w1[2 * c], h3.x, aB3);
            aA0 = fma2(w0[2 * c + 1], h0.y, aA0);
            aA1 = fma2(w0[2 * c + 1], h1.y, aA1);
            aA2 = fma2(w0[2 * c + 1], h2.y, aA2);
            aA3 = fma2(w0[2 * c + 1], h3.y, aA3);
            aB0 = fma2(w1[2 * c + 1], h0.y, aB0);
            aB1 = fma2(w1[2 * c + 1], h1.y, aB1);
            aB2 = fma2(w1[2 * c + 1], h2.y, aB2);
            aB3 = fma2(w1[2 * c + 1], h3.y, aB3);
        }
        // pair-summed partials, float2-packed {row rp, row rp+64}
        if (q == 0) {
            psv[buf][0][0][rp] = make_float2(lo32(aA0) + hi32(aA0) + xwA0,
                                             lo32(aB0) + hi32(aB0) + xwB0);
            psv[buf][0][1][rp] = make_float2(lo32(aA1) + hi32(aA1) + xwA1,
                                             lo32(aB1) + hi32(aB1) + xwB1);
            psv[buf][0][2][rp] = make_float2(lo32(aA2) + hi32(aA2) + xwA2,
                                             lo32(aB2) + hi32(aB2) + xwB2);
            psv[buf][0][3][rp] = make_float2(lo32(aA3) + hi32(aA3) + xwA3,
                                             lo32(aB3) + hi32(aB3) + xwB3);
            xwA0 = xnA0; xwA1 = xnA1; xwA2 = xnA2; xwA3 = xnA3;
            xwB0 = xnB0; xwB1 = xnB1; xwB2 = xnB2; xwB3 = xnB3;
        } else {
            psv[buf][q][0][rp] = make_float2(lo32(aA0) + hi32(aA0),
                                             lo32(aB0) + hi32(aB0));
            psv[buf][q][1][rp] = make_float2(lo32(aA1) + hi32(aA1),
                                             lo32(aB1) + hi32(aB1));
            psv[buf][q][2][rp] = make_float2(lo32(aA2) + hi32(aA2),
                                             lo32(aB2) + hi32(aB2));
            psv[buf][q][3][rp] = make_float2(lo32(aA3) + hi32(aA3),
                                             lo32(aB3) + hi32(aB3));
        }

        // SPLIT barrier: producers arrive and keep going; crew syncs.
        if (tid >= 128) {
            bar_arrive_id(1 + buf, NTH);
        } else {
            bar_sync_id(1 + buf, NTH);

            // --- cell: all 4 gates of (h=ch, b=cb) via packed add2 ---
            // psv[.][b][h] = {i,g}; psv[.][b][32+h] = {f,o}
            const unsigned long long* pig =
                (const unsigned long long*)&psv[buf][0][cb][ch];
            const unsigned long long* pfo =
                (const unsigned long long*)&psv[buf][0][cb][32 + ch];
            const int strd = GB * 64;  // u64 elements between eighths
            unsigned long long ig = add2(add2(pig[0], pig[strd]),
                                         add2(pig[2 * strd], pig[3 * strd]));
            ig = add2(ig, add2(add2(pig[4 * strd], pig[5 * strd]),
                               add2(pig[6 * strd], pig[7 * strd])));
            unsigned long long fo = add2(add2(pfo[0], pfo[strd]),
                                         add2(pfo[2 * strd], pfo[3 * strd]));
            fo = add2(fo, add2(add2(pfo[4 * strd], pfo[5 * strd]),
                               add2(pfo[6 * strd], pfo[7 * strd])));
            float i_ = sigf(lo32(ig));
            float g_ = tanhf_(hi32(ig));
            float f_ = sigf(lo32(fo));
            float o_ = sigf(hi32(fo));
            float cn = f_ * creg + i_ * g_;
            float hn = o_ * tanhf_(cn);
            if (t < mylen) { creg = cn; hreg = hn; }

            if (t + 1 < steps) {
                // gather 4 consecutive-h values into lane 4j, one 16-B
                // st.async per destination rank.
                float v1 = __shfl_down_sync(0xffffffffu, hreg, 1);
                float v2 = __shfl_down_sync(0xffffffffu, hreg, 2);
                float v3 = __shfl_down_sync(0xffffffffu, hreg, 3);
                if ((lane & 3) == 0) {
                    const int nb = buf ^ 1;
                    const unsigned dloc = smem_u32(&hb[nb][cb][base + ch]);
                    const unsigned mloc = nb ? mb1 : mb0;
#pragma unroll
                    for (int r = 0; r < CL; r++) {
                        st_async_f32x4(mapa_u32(dloc, r), hreg, v1, v2, v3,
                                       mapa_u32(mloc, r));
                    }
                }
            }
        }
    }

    if (tid < 128)
        out[(b0 + cb) * HIDN + base + ch] = hreg;
}

// ---------------------------------------------------------------------------
extern "C" void kernel_launch(void* const* d_in, const int* in_sizes, int n_in,
                              void* d_out, int out_size)
{
    const int*   tokens  = (const int*)d_in[0];
    const int*   lengths = (const int*)d_in[1];
    const float* emb     = (const float*)d_in[2];
    const float* W_ih    = (const float*)d_in[3];
    const float* W_hh    = (const float*)d_in[4];
    const float* b_ih    = (const float*)d_in[5];
    const float* b_hh    = (const float*)d_in[6];
    float* out = (float*)d_out;

    proj_kernel<<<VOCABN / 8, 256>>>(emb, W_ih, b_ih, b_hh);

    dim3 grid(CL, BN / GB);
    lstm_kernel<<<grid, NTH>>>(tokens, lengths, W_hh, out);
}

// round 17
// speedup vs baseline: 1.6114x; 1.6114x over previous
#include <cuda_runtime.h>

#define VOCABN 1000
#define EMBN   128
#define HIDN   256
#define G4N    1024   // 4*HID
#define BN     64
#define TN     1024

#define CL     8      // CTAs per cluster
#define GB     4      // batch rows per cluster
#define NTH    512    // 32 h-indices x 16 k-sixteenths

// Precomputed per-vocab gate projections: proj[v][g] = emb[v].W_ih[g] + b_ih[g] + b_hh[g]
__device__ float g_proj[VOCABN * G4N];

// ---------------- packed f32x2 helpers ----------------
__device__ __forceinline__ unsigned long long fma2(unsigned long long a,
                                                   unsigned long long b,
                                                   unsigned long long c) {
    unsigned long long d;
    asm("fma.rn.f32x2 %0, %1, %2, %3;" : "=l"(d) : "l"(a), "l"(b), "l"(c));
    return d;
}
__device__ __forceinline__ unsigned long long add2(unsigned long long a,
                                                   unsigned long long b) {
    unsigned long long d;
    asm("add.rn.f32x2 %0, %1, %2;" : "=l"(d) : "l"(a), "l"(b));
    return d;
}
__device__ __forceinline__ float lo32(unsigned long long v) {
    return __uint_as_float((unsigned)v);
}
__device__ __forceinline__ float hi32(unsigned long long v) {
    return __uint_as_float((unsigned)(v >> 32));
}

__device__ __forceinline__ float sigf(float x) {
    return __fdividef(1.0f, 1.0f + __expf(-x));
}
__device__ __forceinline__ float tanhf_(float x) {
    return 1.0f - __fdividef(2.0f, __expf(2.0f * x) + 1.0f);
}

// ---------------- cluster smem / mbarrier helpers ----------------
__device__ __forceinline__ unsigned smem_u32(const void* p) {
    return (unsigned)__cvta_generic_to_shared(p);
}
__device__ __forceinline__ void mbar_init(unsigned a, unsigned cnt) {
    asm volatile("mbarrier.init.shared.b64 [%0], %1;" :: "r"(a), "r"(cnt) : "memory");
}
__device__ __forceinline__ unsigned mapa_u32(unsigned a, unsigned rank) {
    unsigned r;
    asm("mapa.shared::cluster.u32 %0, %1, %2;" : "=r"(r) : "r"(a), "r"(rank));
    return r;
}
__device__ __forceinline__ void mbar_arm(unsigned a, unsigned tx_bytes) {
    asm volatile("mbarrier.arrive.expect_tx.shared.b64 _, [%0], %1;"
                 :: "r"(a), "r"(tx_bytes) : "memory");
}
// remote vector store (16 B), counts bytes into the destination's mbarrier
__device__ __forceinline__ void st_async_f32x4(unsigned dst, float v0, float v1,
                                               float v2, float v3, unsigned mb) {
    asm volatile(
        "st.async.shared::cluster.mbarrier::complete_tx::bytes.v4.b32 "
        "[%0], {%1, %2, %3, %4}, [%5];"
        :: "r"(dst), "r"(__float_as_uint(v0)), "r"(__float_as_uint(v1)),
           "r"(__float_as_uint(v2)), "r"(__float_as_uint(v3)), "r"(mb)
        : "memory");
}
__device__ __forceinline__ void mbar_wait(unsigned a, unsigned parity) {
    asm volatile(
        "{\n\t"
        ".reg .pred P;\n\t"
        "mbarrier.try_wait.parity.acquire.cluster.shared::cta.b64 P, [%0], %1;\n\t"
        "@P bra.uni WDONE_%=;\n\t"
        "WLOOP_%=:\n\t"
        "mbarrier.try_wait.parity.acquire.cluster.shared::cta.b64 P, [%0], %1, 0x989680;\n\t"
        "@!P bra.uni WLOOP_%=;\n\t"
        "WDONE_%=:\n\t"
        "}"
        :: "r"(a), "r"(parity) : "memory");
}
__device__ __forceinline__ void cluster_sync_once() {
    asm volatile("barrier.cluster.arrive.aligned;" ::: "memory");
    asm volatile("barrier.cluster.wait.aligned;" ::: "memory");
}

// ---------------------------------------------------------------------------
// Kernel 1: vocab projection table. 125 blocks x 256 threads, 8 vocab/block.
// ---------------------------------------------------------------------------
__global__ void __launch_bounds__(256) proj_kernel(
    const float* __restrict__ emb, const float* __restrict__ W_ih,
    const float* __restrict__ b_ih, const float* __restrict__ b_hh)
{
    __shared__ float4 es4[8][EMBN / 4];
    const int v0 = blockIdx.x * 8;
    const int tid = threadIdx.x;
    for (int i = tid; i < 8 * EMBN; i += 256) {
        int v = i >> 7, e = i & 127;
        ((float*)es4)[v * EMBN + e] = emb[(v0 + v) * EMBN + e];
    }
    __syncthreads();

    const float4* W4 = (const float4*)W_ih;
#pragma unroll
    for (int rr = 0; rr < 4; rr++) {
        int g = tid + rr * 256;
        float acc[8];
#pragma unroll
        for (int v = 0; v < 8; v++) acc[v] = 0.f;
        for (int e4 = 0; e4 < EMBN / 4; e4++) {
            float4 w = W4[g * (EMBN / 4) + e4];
#pragma unroll
            for (int v = 0; v < 8; v++) {
                float4 x = es4[v][e4];
                acc[v] += w.x * x.x + w.y * x.y + w.z * x.z + w.w * x.w;
            }
        }
        float bias = b_ih[g] + b_hh[g];
#pragma unroll
        for (int v = 0; v < 8; v++)
            g_proj[(v0 + v) * G4N + g] = acc[v] + bias;
    }
}

// ---------------------------------------------------------------------------
// Kernel 2: recurrence. 16 clusters x 8 CTAs; cluster owns 4 batch rows.
// Thread = (h-index rq 0..31, k-sixteenth q = tid>>5 — warp-uniform).
// Each thread computes ALL FOUR gate rows of its h-index (i,f,g,o) over a
// 16-float k-chunk: 16 LDS.128 + 128 FFMA2 per thread — each h load feeds
// 8 FMAs. psum[q][batch][h] is a float4 holding all 4 gates of that h, so
// the cell thread sums 16 float4s (packed add2, conflict-free LDS.128) and
// needs NO gate shuffle. xproj is loaded by the cell crew (4 prefetched
// L2-hit LDGs), removing all special-casing from producers. Exchange:
// st.async.v4 + double-buffered tx mbarriers (R14/R15 proven path).
// ---------------------------------------------------------------------------
__global__ void __launch_bounds__(NTH, 1) __cluster_dims__(CL, 1, 1)
lstm_kernel(const int* __restrict__ tokens, const int* __restrict__ lengths,
            const float* __restrict__ W_hh, float* __restrict__ out)
{
    __shared__ float  hb[2][GB][HIDN];         // 8 KB: double-buffered h, batch-major
    __shared__ float4 psv[16][GB][32];         // 32 KB: [sixteenth][batch][h] = 4 gates
    __shared__ __align__(8) unsigned long long mbar[2];

    const int rank = blockIdx.x;               // 0..7
    const int cid  = blockIdx.y;               // 0..15
    const int tid  = threadIdx.x;
    const int rq   = tid & 31;                 // h-index 0..31
    const int q    = tid >> 5;                 // k-sixteenth 0..15 (warp-uniform)
    const int base = rank * 32;
    const int b0   = cid * GB;
    const unsigned TXB = 4096;                 // bytes per exchange phase

    // --- W slices into registers: 4 gate rows x 16 floats = 32 u64 ---
    unsigned long long wg[4][8];
#pragma unroll
    for (int g = 0; g < 4; g++) {
        const int grow = g * HIDN + base + rq;
        const ulonglong2* wr =
            (const ulonglong2*)(W_hh + (size_t)grow * HIDN + q * 16);
#pragma unroll
        for (int j = 0; j < 4; j++) {
            ulonglong2 v = wr[j];
            wg[g][2 * j]     = v.x;
            wg[g][2 * j + 1] = v.y;
        }
    }

    const unsigned mb0 = smem_u32(&mbar[0]);
    const unsigned mb1 = smem_u32(&mbar[1]);
    if (tid == 0) {
        mbar_init(mb0, 1);
        mbar_init(mb1, 1);
        mbar_arm(mb1, TXB);    // pre-arm for t=1 data (arrives into hb[1])
    }
    for (int i = tid; i < GB * HIDN; i += NTH) ((float*)hb[0])[i] = 0.f;
    __syncthreads();
    cluster_sync_once();       // init + hb[0]=0 visible cluster-wide

    // cell crew identity (tid<128): one thread per (h index, batch)
    const int ch = tid & 31;        // h index
    const int cb = tid >> 5;        // batch 0..3 (for tid<128)
    const int mylen = (tid < 128) ? lengths[b0 + cb] : 0;
    const bool crew = (tid < 128);

    const int len0 = lengths[b0 + 0];
    const int len1 = lengths[b0 + 1];
    const int len2 = lengths[b0 + 2];
    const int len3 = lengths[b0 + 3];
    int steps = max(max(len0, len1), max(len2, len3));
    if (steps > TN) steps = TN;

    // input projections: cell crew holds 4 gates of its (h, b)
    float xc0 = 0.f, xc1 = 0.f, xc2 = 0.f, xc3 = 0.f;
    if (crew) {
        const int tok = tokens[(b0 + cb) * TN];
        const int gi  = tok * G4N + base + ch;
        xc0 = g_proj[gi];
        xc1 = g_proj[gi + HIDN];
        xc2 = g_proj[gi + 2 * HIDN];
        xc3 = g_proj[gi + 3 * HIDN];
    }

    float creg = 0.f, hreg = 0.f;
    unsigned ph0 = 0, ph1 = 0;
    const int lane = tid & 31;

    for (int t = 0; t < steps; t++) {
        const int buf = t & 1;
        // wait for h(t) (skip t=0: hb[0] prezeroed), then re-arm this barrier
        // for the phase two steps ahead.
        if (t) {
            if (buf) { mbar_wait(mb1, ph1); ph1 ^= 1; }
            else     { mbar_wait(mb0, ph0); ph0 ^= 1; }
        }
        if (tid == 0) mbar_arm(buf ? mb1 : mb0, TXB);

        // crew prefetches next step's input projections (L2 latency hidden)
        float xn0, xn1, xn2, xn3;
        if (crew) {
            const int tn  = min(t + 1, TN - 1);
            const int tok = tokens[(b0 + cb) * TN + tn];
            const int gi  = tok * G4N + base + ch;
            xn0 = g_proj[gi];
            xn1 = g_proj[gi + HIDN];
            xn2 = g_proj[gi + 2 * HIDN];
            xn3 = g_proj[gi + 3 * HIDN];
        }

        // packed matvec: 4 gate rows of h=rq, my k-sixteenth, 4 batches.
        // 16 LDS.128 + 128 FFMA2: each h load feeds 8 FMAs.
        const float* h0p = hb[buf][0] + q * 16;
        const float* h1p = hb[buf][1] + q * 16;
        const float* h2p = hb[buf][2] + q * 16;
        const float* h3p = hb[buf][3] + q * 16;
        unsigned long long acc[4][4];   // [gate][batch]
#pragma unroll
        for (int g = 0; g < 4; g++)
#pragma unroll
            for (int b = 0; b < 4; b++) acc[g][b] = 0ull;
#pragma unroll
        for (int c = 0; c < 4; c++) {
            ulonglong2 h0 = *(const ulonglong2*)(h0p + c * 4);
            ulonglong2 h1 = *(const ulonglong2*)(h1p + c * 4);
            ulonglong2 h2 = *(const ulonglong2*)(h2p + c * 4);
            ulonglong2 h3 = *(const ulonglong2*)(h3p + c * 4);
#pragma unroll
            for (int g = 0; g < 4; g++) {
                acc[g][0] = fma2(wg[g][2 * c], h0.x, acc[g][0]);
                acc[g][1] = fma2(wg[g][2 * c], h1.x, acc[g][1]);
                acc[g][2] = fma2(wg[g][2 * c], h2.x, acc[g][2]);
                acc[g][3] = fma2(wg[g][2 * c], h3.x, acc[g][3]);
                acc[g][0] = fma2(wg[g][2 * c + 1], h0.y, acc[g][0]);
                acc[g][1] = fma2(wg[g][2 * c + 1], h1.y, acc[g][1]);
                acc[g][2] = fma2(wg[g][2 * c + 1], h2.y, acc[g][2]);
                acc[g][3] = fma2(wg[g][2 * c + 1], h3.y, acc[g][3]);
            }
        }
        // pair-summed partials: float4 = {i,f,g,o} of h=rq for each batch
#pragma unroll
        for (int b = 0; b < 4; b++) {
            psv[q][b][rq] = make_float4(
                lo32(acc[0][b]) + hi32(acc[0][b]),
                lo32(acc[1][b]) + hi32(acc[1][b]),
                lo32(acc[2][b]) + hi32(acc[2][b]),
                lo32(acc[3][b]) + hi32(acc[3][b]));
        }
        __syncthreads();

        // cell update on tid<128: sum 16 packed partials, all gates in-thread.
        if (crew) {
            const unsigned long long* pp =
                (const unsigned long long*)&psv[0][cb][ch];
            const int strd = GB * 32 * 2;   // u64 elements between sixteenths
            unsigned long long sx = pp[0], sy = pp[1];
#pragma unroll
            for (int sgm = 1; sgm < 16; sgm++) {
                sx = add2(sx, pp[sgm * strd]);
                sy = add2(sy, pp[sgm * strd + 1]);
            }
            float i_ = sigf(lo32(sx) + xc0);
            float f_ = sigf(hi32(sx) + xc1);
            float g_ = tanhf_(lo32(sy) + xc2);
            float o_ = sigf(hi32(sy) + xc3);
            float cn = f_ * creg + i_ * g_;
            float hn = o_ * tanhf_(cn);
            if (t < mylen) { creg = cn; hreg = hn; }
            xc0 = xn0; xc1 = xn1; xc2 = xn2; xc3 = xn3;

            if (t + 1 < steps) {
                // gather 4 consecutive-h values into lane 4j, one 16-B
                // st.async per destination rank.
                float v1 = __shfl_down_sync(0xffffffffu, hreg, 1);
                float v2 = __shfl_down_sync(0xffffffffu, hreg, 2);
                float v3 = __shfl_down_sync(0xffffffffu, hreg, 3);
                if ((lane & 3) == 0) {
                    const int nb = buf ^ 1;
                    const unsigned dloc = smem_u32(&hb[nb][cb][base + ch]);
                    const unsigned mloc = nb ? mb1 : mb0;
#pragma unroll
                    for (int r = 0; r < CL; r++) {
                        st_async_f32x4(mapa_u32(dloc, r), hreg, v1, v2, v3,
                                       mapa_u32(mloc, r));
                    }
                }
            }
        }
    }

    if (crew)
        out[(b0 + cb) * HIDN + base + ch] = hreg;
}

// ---------------------------------------------------------------------------
extern "C" void kernel_launch(void* const* d_in, const int* in_sizes, int n_in,
                              void* d_out, int out_size)
{
    const int*   tokens  = (const int*)d_in[0];
    const int*   lengths = (const int*)d_in[1];
    const float* emb     = (const float*)d_in[2];
    const float* W_ih    = (const float*)d_in[3];
    const float* W_hh    = (const float*)d_in[4];
    const float* b_ih    = (const float*)d_in[5];
    const float* b_hh    = (const float*)d_in[6];
    float* out = (float*)d_out;

    proj_kernel<<<VOCABN / 8, 256>>>(emb, W_ih, b_ih, b_hh);

    dim3 grid(CL, BN / GB);
    lstm_kernel<<<grid, NTH>>>(tokens, lengths, W_hh, out);
}